// round 7
// baseline (speedup 1.0000x reference)
#include <cuda_runtime.h>
#include <cuda_fp16.h>
#include <math.h>

// Problem constants (fixed by the reference)
#define NV 100000
#define NB 8
#define TILE_V 128
#define NTILES ((NV + TILE_V - 1) / TILE_V)   // 782
#define EBLK (148 * 6)                         // edge-kernel grid: 6 blocks/SM
#define NWARPS (EBLK * 8)

// Scratch: 12B fp16 record per (v,b), split for aligned vector access:
//   g_va[(v*NB+b)] = uint2{ half2(x0,x1), half2(x2,dx0) }   (8B)
//   g_vb[(v*NB+b)] = uint { half2(dx1,dx2) }                 (4B)
// One vertex = 64B + 32B. Total 9.6 MB (L2-resident).
__device__ uint2 g_va[(size_t)NV * NB];
__device__ unsigned int g_vb[(size_t)NV * NB];
__device__ double g_acc[NB];             // zero-init; reset by edge kernel's final block
__device__ unsigned g_done;              // zero-init; reset by edge kernel's final block

// ---------------------------------------------------------------------------
// Kernel A: transpose (B, NV, 3) x2 -> split fp16 records. One tile per block.
// ---------------------------------------------------------------------------
__global__ void __launch_bounds__(256, 4)
prep_kernel(const float* __restrict__ dx, const float* __restrict__ x) {
    __shared__ float4 sx4[NB][TILE_V * 3 / 4 + 1];   // [8][97]
    __shared__ float4 sdx4[NB][TILE_V * 3 / 4 + 1];

    const int tid = threadIdx.x;
    const int v0 = blockIdx.x * TILE_V;
    const int nv = min(TILE_V, NV - v0);
    const int nf4 = nv * 3 / 4;

    // Read: 8 batch rows x 96 float4s each, coalesced.
    #pragma unroll
    for (int k = 0; k < 3; k++) {
        int i = k * 256 + tid;                // [0, 768)
        int b = i / 96;
        int j = i - b * 96;
        size_t g4 = (size_t)b * (NV * 3 / 4) + (size_t)v0 * 3 / 4 + j;
        if (j < nf4) {
            sx4[b][j]  = ((const float4*)x)[g4];
            sdx4[b][j] = ((const float4*)dx)[g4];
        }
    }
    __syncthreads();

    const float* sxf  = (const float*)sx4;
    const float* sdxf = (const float*)sdx4;
    const int ROWF = (TILE_V * 3 / 4 + 1) * 4;        // 388 floats per smem row
    // Write: 1024 records (128 v x 8 b), shift-only index math, coalesced streams.
    #pragma unroll
    for (int k = 0; k < 4; k++) {
        int rec = k * 256 + tid;              // [0, 1024)
        int v = rec >> 3;
        int b = rec & (NB - 1);
        if (v < nv) {
            int j = b * ROWF + v * 3;
            __half2 h0 = __floats2half2_rn(sxf[j],      sxf[j + 1]);
            __half2 h1 = __floats2half2_rn(sxf[j + 2],  sdxf[j]);
            __half2 h2 = __floats2half2_rn(sdxf[j + 1], sdxf[j + 2]);
            size_t gidx = (size_t)(v0 + v) * NB + b;
            uint2 r;
            r.x = *(unsigned int*)&h0;
            r.y = *(unsigned int*)&h1;
            g_va[gidx] = r;
            g_vb[gidx] = *(unsigned int*)&h2;
        }
    }
}

// ---------------------------------------------------------------------------
// Kernel B: edge gather + reduce + finalize. Reads es/ed directly (no
// compaction); s<d predicate is uniform within each 8-lane group, so the
// gathers are predicated off for skipped edges. 4-deep unrolled body.
// ---------------------------------------------------------------------------
__device__ __forceinline__ float edge_term(uint2 A, unsigned Bv, uint2 C, unsigned Dv) {
    __half2 e0 = __hsub2(*(__half2*)&C.x, *(__half2*)&A.x);   // (x0, x1) diff
    __half2 e1 = __hsub2(*(__half2*)&C.y, *(__half2*)&A.y);   // (x2, dx0) diff
    __half2 e2 = __hsub2(*(__half2*)&Dv,  *(__half2*)&Bv);    // (dx1, dx2) diff
    float2 f0 = __half22float2(e0);
    float2 f1 = __half22float2(e1);
    float2 f2 = __half22float2(e2);
    float diffx = f0.x * f0.x + f0.y * f0.y + f1.x * f1.x;
    float diffd = f1.y * f1.y + f2.x * f2.x + f2.y * f2.y;
    return fabsf(diffx - diffd);
}

__global__ void __launch_bounds__(256, 6)
edge_kernel(const int* __restrict__ es, const int* __restrict__ ed,
            float* __restrict__ out, int E) {
    __shared__ float sacc[8][9];
    __shared__ bool slast;

    const int tid  = threadIdx.x;
    const int lane = tid & 31;
    const int warp = tid >> 5;
    const int b    = lane & 7;
    const int grp  = lane >> 3;
    const int gwarp = blockIdx.x * 8 + warp;

    const int per   = (E + NWARPS - 1) / NWARPS;     // contiguous directed-edge range
    const int start = gwarp * per;
    const int end   = min(start + per, E);

    float acc = 0.f;
    int e = start + grp;
    for (; e + 12 < end; e += 16) {
        int s0 = es[e],      d0 = ed[e];
        int s1 = es[e + 4],  d1 = ed[e + 4];
        int s2 = es[e + 8],  d2 = ed[e + 8];
        int s3 = es[e + 12], d3 = ed[e + 12];
        bool p0 = s0 < d0, p1 = s1 < d1, p2 = s2 < d2, p3 = s3 < d3;
        uint2 A0, C0, A1, C1, A2, C2, A3, C3;
        unsigned B0, D0, B1, D1, B2, D2, B3, D3;
        if (p0) { unsigned i = (unsigned)s0 * NB + b, j = (unsigned)d0 * NB + b;
                  A0 = g_va[i]; B0 = g_vb[i]; C0 = g_va[j]; D0 = g_vb[j]; }
        if (p1) { unsigned i = (unsigned)s1 * NB + b, j = (unsigned)d1 * NB + b;
                  A1 = g_va[i]; B1 = g_vb[i]; C1 = g_va[j]; D1 = g_vb[j]; }
        if (p2) { unsigned i = (unsigned)s2 * NB + b, j = (unsigned)d2 * NB + b;
                  A2 = g_va[i]; B2 = g_vb[i]; C2 = g_va[j]; D2 = g_vb[j]; }
        if (p3) { unsigned i = (unsigned)s3 * NB + b, j = (unsigned)d3 * NB + b;
                  A3 = g_va[i]; B3 = g_vb[i]; C3 = g_va[j]; D3 = g_vb[j]; }
        if (p0) acc += edge_term(A0, B0, C0, D0);
        if (p1) acc += edge_term(A1, B1, C1, D1);
        if (p2) acc += edge_term(A2, B2, C2, D2);
        if (p3) acc += edge_term(A3, B3, C3, D3);
    }
    for (; e < end; e += 4) {
        int s = es[e], d = ed[e];
        if (s < d) {
            unsigned i = (unsigned)s * NB + b, j = (unsigned)d * NB + b;
            acc += edge_term(g_va[i], g_vb[i], g_va[j], g_vb[j]);
        }
    }

    acc += __shfl_xor_sync(0xffffffff, acc, 8);
    acc += __shfl_xor_sync(0xffffffff, acc, 16);

    if (lane < 8) sacc[warp][b] = acc;
    __syncthreads();
    if (warp == 0 && lane < 8) {
        float s = 0.f;
        #pragma unroll
        for (int w = 0; w < 8; w++) s += sacc[w][lane];
        atomicAdd(&g_acc[lane], (double)s);
    }
    __syncthreads();

    // last-block finalize + state reset (keeps launches deterministic)
    if (tid == 0) {
        __threadfence();
        slast = (atomicAdd(&g_done, 1u) == EBLK - 1);
    }
    __syncthreads();
    if (slast) {
        if (tid < NB) {
            double a = *(volatile double*)&g_acc[tid];
            out[tid] = (float)(2.0 * a / (double)E);
            g_acc[tid] = 0.0;
        }
        if (tid == NB) g_done = 0;
    }
}

extern "C" void kernel_launch(void* const* d_in, const int* in_sizes, int n_in,
                              void* d_out, int out_size) {
    // metadata order: dx, x, edge_src, edge_dst
    const float* dx = (const float*)d_in[0];
    const float* x  = (const float*)d_in[1];
    const int* es   = (const int*)d_in[2];
    const int* ed   = (const int*)d_in[3];
    float* out      = (float*)d_out;
    const int E     = in_sizes[2];

    prep_kernel<<<NTILES, 256>>>(dx, x);
    edge_kernel<<<EBLK, 256>>>(es, ed, out, E);
}

// round 8
// speedup vs baseline: 1.2279x; 1.2279x over previous
#include <cuda_runtime.h>
#include <cuda_fp16.h>
#include <math.h>

// Problem constants (fixed by the reference)
#define NV 100000
#define NB 8
#define TILE_V 128
#define NTILES ((NV + TILE_V - 1) / TILE_V)   // 782
#define NBLK 592                               // prep grid: 148 SMs x 4
#define TBLK 400                               // transpose blocks in prep
#define CBLK (NBLK - TBLK)                     // compact blocks in prep
#define CHUNK 2048
#define EMAX 1200064
#define EBLK (148 * 6)                         // edge grid: 6 blocks/SM
#define EWARPS (EBLK * 8)

// Scratch: 16B fp16 record per (v,b): half2{x0,x1}, half2{x2,dx0}, half2{dx1,dx2}, pad.
// One vertex = 8 records = 128B line. Total 12.8 MB (L2-resident).
__device__ uint4 g_v[(size_t)NV * NB];
__device__ int2 g_edges[EMAX / 2 + 128];
__device__ int g_ecount;                 // zero-init; reset by edge kernel's final block
__device__ double g_acc[NB];             // zero-init; reset by edge kernel's final block
__device__ unsigned g_done;              // zero-init; reset by edge kernel's final block

// ---------------------------------------------------------------------------
// Kernel A: transpose (blocks [0,TBLK)) overlapped with s<d edge compaction
// (blocks [TBLK,NBLK)). Kernel boundary is the phase barrier.
// ---------------------------------------------------------------------------
__global__ void __launch_bounds__(256, 4)
prep_kernel(const float* __restrict__ dx, const float* __restrict__ x,
            const int* __restrict__ es, const int* __restrict__ ed, int E) {
    __shared__ float4 sx4[NB][TILE_V * 3 / 4 + 1];   // [8][97]
    __shared__ float4 sdx4[NB][TILE_V * 3 / 4 + 1];
    __shared__ int wsum[8];
    __shared__ int sbase;

    const int tid  = threadIdx.x;
    const int bid  = blockIdx.x;
    const int lane = tid & 31;
    const int warp = tid >> 5;

    if (bid < TBLK) {
        for (int t = bid; t < NTILES; t += TBLK) {
            const int v0 = t * TILE_V;
            const int nv = min(TILE_V, NV - v0);
            const int nf4 = nv * 3 / 4;
            #pragma unroll
            for (int k = 0; k < 3; k++) {
                int i = k * 256 + tid;                // [0, 768)
                int b = i / 96;
                int j = i - b * 96;
                size_t g4 = (size_t)b * (NV * 3 / 4) + (size_t)v0 * 3 / 4 + j;
                if (j < nf4) {
                    sx4[b][j]  = ((const float4*)x)[g4];
                    sdx4[b][j] = ((const float4*)dx)[g4];
                }
            }
            __syncthreads();
            const float* sxf  = (const float*)sx4;
            const float* sdxf = (const float*)sdx4;
            const int ROWF = (TILE_V * 3 / 4 + 1) * 4;
            uint4* outp = g_v + (size_t)v0 * NB;
            #pragma unroll
            for (int k = 0; k < 4; k++) {
                int rec = k * 256 + tid;              // [0, 1024)
                int v = rec >> 3;
                int b = rec & (NB - 1);
                if (v < nv) {
                    int j = b * ROWF + v * 3;
                    __half2 h0 = __floats2half2_rn(sxf[j],      sxf[j + 1]);
                    __half2 h1 = __floats2half2_rn(sxf[j + 2],  sdxf[j]);
                    __half2 h2 = __floats2half2_rn(sdxf[j + 1], sdxf[j + 2]);
                    uint4 r;
                    r.x = *(unsigned int*)&h0;
                    r.y = *(unsigned int*)&h1;
                    r.z = *(unsigned int*)&h2;
                    r.w = 0u;
                    outp[rec] = r;
                }
            }
            __syncthreads();
        }
    } else {
        const int cid = bid - TBLK;
        const int nchunks = (E + CHUNK - 1) / CHUNK;
        for (int c = cid; c < nchunks; c += CBLK) {
            const int base = c * CHUNK;
            int s[8], d[8];
            bool f[8];
            int cnt = 0;
            #pragma unroll
            for (int k = 0; k < 8; k++) {
                int e = base + k * 256 + tid;
                bool fl = false; int ss = 0, dd = 0;
                if (e < E) { ss = es[e]; dd = ed[e]; fl = ss < dd; }
                s[k] = ss; d[k] = dd; f[k] = fl; cnt += fl;
            }
            int inc = cnt;
            #pragma unroll
            for (int o = 1; o < 32; o <<= 1) {
                int t2 = __shfl_up_sync(0xffffffffu, inc, o);
                if (lane >= o) inc += t2;
            }
            if (lane == 31) wsum[warp] = inc;
            __syncthreads();
            if (tid == 0) {
                int tot = 0;
                #pragma unroll
                for (int w = 0; w < 8; w++) { int t2 = wsum[w]; wsum[w] = tot; tot += t2; }
                sbase = atomicAdd(&g_ecount, tot);
            }
            __syncthreads();
            int pos = sbase + wsum[warp] + (inc - cnt);
            #pragma unroll
            for (int k = 0; k < 8; k++)
                if (f[k]) g_edges[pos++] = make_int2(s[k], d[k]);
            __syncthreads();
        }
    }
}

// ---------------------------------------------------------------------------
// Kernel B: edge gather + reduce + finalize.
// Contiguous per-warp edge ranges (src locality -> L1 hits), one LDG.128 per
// endpoint, unroll x2 to keep regs <= 42 so 6 blocks/SM are resident.
// ---------------------------------------------------------------------------
__device__ __forceinline__ float edge_term(uint4 rs, uint4 rd) {
    __half2 e0 = __hsub2(*(__half2*)&rd.x, *(__half2*)&rs.x);
    __half2 e1 = __hsub2(*(__half2*)&rd.y, *(__half2*)&rs.y);
    __half2 e2 = __hsub2(*(__half2*)&rd.z, *(__half2*)&rs.z);
    float2 f0 = __half22float2(e0);
    float2 f1 = __half22float2(e1);
    float2 f2 = __half22float2(e2);
    float diffx = f0.x * f0.x + f0.y * f0.y + f1.x * f1.x;
    float diffd = f1.y * f1.y + f2.x * f2.x + f2.y * f2.y;
    return fabsf(diffx - diffd);
}

__global__ void __launch_bounds__(256, 6)
edge_kernel(float* __restrict__ out, int E) {
    __shared__ float sacc[8][9];
    __shared__ bool slast;

    const int tid  = threadIdx.x;
    const int lane = tid & 31;
    const int warp = tid >> 5;
    const int b    = lane & 7;
    const int grp  = lane >> 3;
    const int gwarp = blockIdx.x * 8 + warp;

    const int EC  = *(volatile int*)&g_ecount;
    const int per = (EC + EWARPS - 1) / EWARPS;    // ~85 contiguous edges per warp
    const int start = gwarp * per;
    const int end   = min(start + per, EC);

    float acc = 0.f;
    int e = start + grp;
    for (; e + 4 < end; e += 8) {
        int2 sd0 = g_edges[e];
        int2 sd1 = g_edges[e + 4];
        uint4 a0 = g_v[(unsigned)sd0.x * NB + b];
        uint4 c0 = g_v[(unsigned)sd0.y * NB + b];
        uint4 a1 = g_v[(unsigned)sd1.x * NB + b];
        uint4 c1 = g_v[(unsigned)sd1.y * NB + b];
        acc += edge_term(a0, c0);
        acc += edge_term(a1, c1);
    }
    for (; e < end; e += 4) {
        int2 sd = g_edges[e];
        uint4 rs = g_v[(unsigned)sd.x * NB + b];
        uint4 rd = g_v[(unsigned)sd.y * NB + b];
        acc += edge_term(rs, rd);
    }

    acc += __shfl_xor_sync(0xffffffff, acc, 8);
    acc += __shfl_xor_sync(0xffffffff, acc, 16);

    if (lane < 8) sacc[warp][b] = acc;
    __syncthreads();
    if (warp == 0 && lane < 8) {
        float s = 0.f;
        #pragma unroll
        for (int w = 0; w < 8; w++) s += sacc[w][lane];
        atomicAdd(&g_acc[lane], (double)s);
    }
    __syncthreads();

    // last-block finalize + state reset (keeps launches deterministic)
    if (tid == 0) {
        __threadfence();
        slast = (atomicAdd(&g_done, 1u) == EBLK - 1);
    }
    __syncthreads();
    if (slast) {
        if (tid < NB) {
            double a = *(volatile double*)&g_acc[tid];
            out[tid] = (float)(2.0 * a / (double)E);
            g_acc[tid] = 0.0;
        }
        if (tid == NB) g_ecount = 0;
        if (tid == NB + 1) g_done = 0;
    }
}

extern "C" void kernel_launch(void* const* d_in, const int* in_sizes, int n_in,
                              void* d_out, int out_size) {
    // metadata order: dx, x, edge_src, edge_dst
    const float* dx = (const float*)d_in[0];
    const float* x  = (const float*)d_in[1];
    const int* es   = (const int*)d_in[2];
    const int* ed   = (const int*)d_in[3];
    float* out      = (float*)d_out;
    const int E     = in_sizes[2];

    prep_kernel<<<NBLK, 256>>>(dx, x, es, ed, E);
    edge_kernel<<<EBLK, 256>>>(out, E);
}